// round 9
// baseline (speedup 1.0000x reference)
#include <cuda_runtime.h>

// ClassCaps: votes[b,h,w,i,o,m,p] = sum_n poses[b,h,w,i,m,n] * weight[i,o,n,p]
//            + (m==0,p==3)? xv[h,w] ; + (m==1,p==3)? yv[h,w]
// acts passthrough. Output = concat(votes.flatten(), acts.flatten()).
//
// R9: same mapping as R8 but KC=2 + launch_bounds(256,6) -> ~40 regs,
// occupancy 43.6% -> ~75%. Trades some LDS amortization (L1 ~50 -> ~70%)
// for 1.7x more warps-in-flight to feed the DRAM write stream (the current
// limiter: nothing saturated, occ-starved).

#define CB   64
#define CH   14
#define CW   14
#define CIN  32
#define CO   10
#define NCAP (CB*CH*CW*CIN)               // 401408 capsules
#define KC   2                            // capsules per thread
#define NTH  (NCAP*8/KC)                  // 1605632 threads
#define NBLK (NTH/256)                    // 6272 blocks
#define NV   ((long long)NCAP * CO * 16)  // 64225280 vote floats
#define WP   36                           // padded i-stride (float4 units)

__global__ __launch_bounds__(256, 6) void classcaps_kernel(
    const float4* __restrict__ poses4,   // [NCAP*4] float4 (rows m)
    const float*  __restrict__ acts,     // [NCAP]
    const float4* __restrict__ wg4,      // [CIN*CO*4] float4, gmem layout i,o,n
    const float*  __restrict__ xv,       // [H*W]
    const float*  __restrict__ yv,       // [H*W]
    float4*       __restrict__ votes4,   // [NCAP*40]
    float*        __restrict__ acts_out) // [NCAP]
{
    // Stage weight into smem: wsm[(n*CO + o)*WP + i], float4 over p.
    __shared__ float4 wsm[4 * CO * WP];  // 1440 float4 = 22.5KB
    const int t = threadIdx.x;
    for (int j = t; j < CIN * CO * 4; j += 256) {
        float4 v = wg4[j];
        int iw = j / (CO * 4);
        int ow = (j % (CO * 4)) >> 2;
        int nw = j & 3;
        wsm[(nw * CO + ow) * WP + iw] = v;
    }

    // acts passthrough: flat coalesced copy by the low blocks.
    {
        const int g = blockIdx.x * 256 + t;
        if (g * 2 + 1 < NCAP) {
            float2 a = ((const float2*)acts)[g];
            ((float2*)acts_out)[g] = a;
        }
    }
    __syncthreads();

    const int lane   = t & 31;
    const int m      = lane & 3;
    const int olo    = (lane >> 2) & 1;
    const int capsel = (lane >> 3) & 3;
    const int Wg     = blockIdx.x * 8 + (t >> 5);   // global warp id
    const int i      = Wg & 31;                     // caps_in (fixed per warp)
    const int qblk   = Wg >> 5;                     // 0..1567
    const int q0     = qblk * (4 * KC) + capsel;    // base q for this lane

    // Preload K poses, coord-adds, output offsets (branch-free).
    float4 pv[KC];
    float  addw[KC];
    int    off[KC];                                 // float4 index of (cap, m)
    #pragma unroll
    for (int k = 0; k < KC; k++) {
        const int q   = q0 + k * 4;
        const int cap = q * 32 + i;
        pv[k]  = poses4[cap * 4 + m];
        const int hw = q % (CH * CW);
        const float cx = xv[hw], cy = yv[hw];
        addw[k] = (m == 0) ? cx : ((m == 1) ? cy : 0.0f);
        off[k]  = cap * (CO * 4) + m;
    }

    #pragma unroll
    for (int oo = 0; oo < 5; oo++) {
        const int o = 2 * oo + olo;
        // weight rows n=0..3 for (i,o): 2 distinct addrs/warp -> broadcast LDS
        const float4* wp = &wsm[o * WP + i];
        const float4 w0 = wp[0 * CO * WP];
        const float4 w1 = wp[1 * CO * WP];
        const float4 w2 = wp[2 * CO * WP];
        const float4 w3 = wp[3 * CO * WP];

        #pragma unroll
        for (int k = 0; k < KC; k++) {
            const float4 p = pv[k];
            float4 r;
            r.x = p.x*w0.x + p.y*w1.x + p.z*w2.x + p.w*w3.x;
            r.y = p.x*w0.y + p.y*w1.y + p.z*w2.y + p.w*w3.y;
            r.z = p.x*w0.z + p.y*w1.z + p.z*w2.z + p.w*w3.z;
            r.w = p.x*w0.w + p.y*w1.w + p.z*w2.w + p.w*w3.w + addw[k];
            __stcs(votes4 + off[k] + o * 4, r);  // caps x 128B contig/instr
        }
    }
}

extern "C" void kernel_launch(void* const* d_in, const int* in_sizes, int n_in,
                              void* d_out, int out_size) {
    const float4* poses4 = (const float4*)d_in[0];
    const float*  acts   = (const float*)d_in[1];
    const float4* wg4    = (const float4*)d_in[2];
    const float*  xv     = (const float*)d_in[3];
    const float*  yv     = (const float*)d_in[4];
    float* out = (float*)d_out;

    classcaps_kernel<<<NBLK, 256>>>(poses4, acts, wg4, xv, yv,
                                    (float4*)out, out + NV);
}